// round 4
// baseline (speedup 1.0000x reference)
#include <cuda_runtime.h>

// TemporalDecay: out = h + (1-M)*gamma*(h_fwd - h), gamma = exp(-relu(delta*W + b))
// h_fwd[b,t,j] = h[b, t-(delta-1), j], delta in {1..4} clamped to t+1.
// Strategy (R4): strip of 4 consecutive t-rows per thread at one float4 column.
//  - history rows (r-1..r-3) loaded as 3 COALESCED float4s, rotated in registers
//    for the remaining 3 rows of the strip -> zero scattered gathers.
//  - per-lane gamma(2),gamma(3),gamma(4) precomputed in registers (delta==1 => out==h).
//  - all loads batched up front for high MLP; 1.05M threads keep the chip saturated.

#define B_    32
#define T_    2048
#define NVCOL 64              // 256/4 float4 columns per row
#define SEG   4
#define TPB   256

__device__ __forceinline__ float lane_blend(float ha, float p1, float p2, float p3,
                                            float dl, float mm,
                                            float g2, float g3, float g4)
{
    const int di = (int)dl;
    const float hp  = (di == 2) ? p1 : ((di == 3) ? p2 : p3);
    const float gam = (di == 2) ? g2 : ((di == 3) ? g3 : g4);
    const float coef = (mm == 0.0f && di > 1) ? gam : 0.0f;
    return fmaf(coef, hp - ha, ha);
}

__device__ __forceinline__ float4 vec_blend(float4 ha, float4 p1, float4 p2, float4 p3,
                                            float4 dl, float4 mm,
                                            float4 g2, float4 g3, float4 g4)
{
    float4 o;
    o.x = lane_blend(ha.x, p1.x, p2.x, p3.x, dl.x, mm.x, g2.x, g3.x, g4.x);
    o.y = lane_blend(ha.y, p1.y, p2.y, p3.y, dl.y, mm.y, g2.y, g3.y, g4.y);
    o.z = lane_blend(ha.z, p1.z, p2.z, p3.z, dl.z, mm.z, g2.z, g3.z, g4.z);
    o.w = lane_blend(ha.w, p1.w, p2.w, p3.w, dl.w, mm.w, g2.w, g3.w, g4.w);
    return o;
}

__device__ __forceinline__ float gexp(float d, float w, float b)
{
    return __expf(-fmaxf(fmaf(d, w, b), 0.0f));
}

__global__ __launch_bounds__(TPB)
void temporal_decay_kernel(const float4* __restrict__ h4,
                           const float4* __restrict__ d4,
                           const float4* __restrict__ m4,
                           const float4* __restrict__ w4,
                           const float4* __restrict__ b4,
                           float4* __restrict__ out4)
{
    const int gid   = blockIdx.x * TPB + threadIdx.x;
    const int v     = gid & (NVCOL - 1);   // float4 column 0..63
    const int strip = gid >> 6;            // (b*T + t0)/SEG
    const int row0  = strip << 2;          // global row = b*T + t0
    const int t0    = row0 & (T_ - 1);

    // Per-lane gammas for delta = 2,3,4 (delta==1 contributes nothing).
    const float4 ww = w4[v];
    const float4 bb = b4[v];
    float4 g2, g3, g4;
    g2.x = gexp(2.f, ww.x, bb.x); g2.y = gexp(2.f, ww.y, bb.y);
    g2.z = gexp(2.f, ww.z, bb.z); g2.w = gexp(2.f, ww.w, bb.w);
    g3.x = gexp(3.f, ww.x, bb.x); g3.y = gexp(3.f, ww.y, bb.y);
    g3.z = gexp(3.f, ww.z, bb.z); g3.w = gexp(3.f, ww.w, bb.w);
    g4.x = gexp(4.f, ww.x, bb.x); g4.y = gexp(4.f, ww.y, bb.y);
    g4.z = gexp(4.f, ww.z, bb.z); g4.w = gexp(4.f, ww.w, bb.w);

    const size_t hbase = (size_t)row0 * NVCOL + v;
    const size_t dbase = (size_t)row0 * 16 + (v & 15);

    // History for the strip's first row. t0 is a multiple of 4, so either t0==0
    // (delta clamped to 1 -> history unused, clamp indices in-bounds) or t0>=4
    // (rows row0-1..row0-3 are valid and in the same sequence).
    const int ok = (t0 != 0);
    float4 p1 = h4[hbase - (size_t)(ok ? 1 : 0) * NVCOL];
    float4 p2 = h4[hbase - (size_t)(ok ? 2 : 0) * NVCOL];
    float4 p3 = h4[hbase - (size_t)(ok ? 3 : 0) * NVCOL];

    // Batch all remaining loads (independent -> high MLP).
    const float4 a0 = h4[hbase];
    const float4 a1 = h4[hbase + NVCOL];
    const float4 a2 = h4[hbase + 2 * NVCOL];
    const float4 a3 = h4[hbase + 3 * NVCOL];
    const float4 l0 = d4[dbase];
    const float4 l1 = d4[dbase + 16];
    const float4 l2 = d4[dbase + 32];
    const float4 l3 = d4[dbase + 48];
    const float4 q0 = m4[dbase];
    const float4 q1 = m4[dbase + 16];
    const float4 q2 = m4[dbase + 32];
    const float4 q3 = m4[dbase + 48];

    out4[hbase]             = vec_blend(a0, p1, p2, p3, l0, q0, g2, g3, g4);
    out4[hbase + NVCOL]     = vec_blend(a1, a0, p1, p2, l1, q1, g2, g3, g4);
    out4[hbase + 2 * NVCOL] = vec_blend(a2, a1, a0, p1, l2, q2, g2, g3, g4);
    out4[hbase + 3 * NVCOL] = vec_blend(a3, a2, a1, a0, l3, q3, g2, g3, g4);
}

extern "C" void kernel_launch(void* const* d_in, const int* in_sizes, int n_in,
                              void* d_out, int out_size)
{
    const float* h_a    = (const float*)d_in[0];
    const float* deltas = (const float*)d_in[1];
    const float* M      = (const float*)d_in[2];
    const float* W      = (const float*)d_in[3];
    const float* bvec   = (const float*)d_in[4];
    float* out          = (float*)d_out;

    const int nthreads = (B_ * T_ / SEG) * NVCOL;   // 1,048,576
    const int blocks   = nthreads / TPB;            // 4096

    temporal_decay_kernel<<<blocks, TPB>>>(
        (const float4*)h_a, (const float4*)deltas, (const float4*)M,
        (const float4*)W, (const float4*)bvec, (float4*)out);
}

// round 5
// speedup vs baseline: 1.0585x; 1.0585x over previous
#include <cuda_runtime.h>

// TemporalDecay: out = h + (1-M)*gamma*(h_fwd - h), gamma = exp(-relu(delta*W + b))
// h_fwd[b,t,j] = h[b, t-(delta-1), j], delta in {1..4} clamped to t+1.
//
// R5 strategy: keep R1's flat grid (one float4 output per thread, 4.19M threads,
// low regs, high occupancy) but eliminate the scattered scalar gathers:
// load rows r-1, r-2, r-3 as COALESCED float4s and select in registers.
// h (67MB) fits in L2 (126MB), so the 3 history re-reads are L2 hits -> no extra
// DRAM. Every L1 wavefront is a full 128B line, no replays.

#define B_    32
#define T_    2048
#define NVCOL 64              // 256/4 float4 columns per row
#define TPB   256
#define NVEC  (B_ * T_ * NVCOL)   // 4,194,304

__device__ __forceinline__ float lane_blend(float ha, float p1, float p2, float p3,
                                            float dl, float mm, float w, float b)
{
    const int di = (int)dl;
    const float g  = __expf(-fmaxf(fmaf(dl, w, b), 0.0f));
    const float hp = (di == 2) ? p1 : ((di == 3) ? p2 : p3);
    const float coef = (mm == 0.0f && di > 1) ? g : 0.0f;
    return fmaf(coef, hp - ha, ha);
}

__global__ __launch_bounds__(TPB)
void temporal_decay_kernel(const float4* __restrict__ h4,
                           const float4* __restrict__ d4,
                           const float4* __restrict__ m4,
                           const float4* __restrict__ w4,
                           const float4* __restrict__ b4,
                           float4* __restrict__ out4)
{
    const int i   = blockIdx.x * TPB + threadIdx.x;
    const int row = i >> 6;            // global row = b*T + t
    const int v   = i & (NVCOL - 1);   // float4 column

    // History rows, coalesced. Clamp only guards global row < 3 (b=0, t<3);
    // whenever a clamped row would be selected, delta's own clamp (<= t+1)
    // guarantees that element actually selects a valid row instead.
    const int r1 = max(row - 1, 0);
    const int r2 = max(row - 2, 0);
    const int r3 = max(row - 3, 0);

    // Batch all loads up front (independent -> MLP=8).
    const float4 ha = h4[i];
    const float4 p1 = h4[(size_t)r1 * NVCOL + v];
    const float4 p2 = h4[(size_t)r2 * NVCOL + v];
    const float4 p3 = h4[(size_t)r3 * NVCOL + v];
    const float4 dl = d4[(row << 4) + (v & 15)];
    const float4 mm = m4[(row << 4) + (v & 15)];
    const float4 ww = w4[v];
    const float4 bb = b4[v];

    float4 o;
    o.x = lane_blend(ha.x, p1.x, p2.x, p3.x, dl.x, mm.x, ww.x, bb.x);
    o.y = lane_blend(ha.y, p1.y, p2.y, p3.y, dl.y, mm.y, ww.y, bb.y);
    o.z = lane_blend(ha.z, p1.z, p2.z, p3.z, dl.z, mm.z, ww.z, bb.z);
    o.w = lane_blend(ha.w, p1.w, p2.w, p3.w, dl.w, mm.w, ww.w, bb.w);

    out4[i] = o;
}

extern "C" void kernel_launch(void* const* d_in, const int* in_sizes, int n_in,
                              void* d_out, int out_size)
{
    const float* h_a    = (const float*)d_in[0];
    const float* deltas = (const float*)d_in[1];
    const float* M      = (const float*)d_in[2];
    const float* W      = (const float*)d_in[3];
    const float* bvec   = (const float*)d_in[4];
    float* out          = (float*)d_out;

    const int blocks = NVEC / TPB;   // 16384

    temporal_decay_kernel<<<blocks, TPB>>>(
        (const float4*)h_a, (const float4*)deltas, (const float4*)M,
        (const float4*)W, (const float4*)bvec, (float4*)out);
}

// round 6
// speedup vs baseline: 1.2062x; 1.1395x over previous
#include <cuda_runtime.h>

// TemporalDecay: out = h + (1-M)*gamma*(h_fwd - h), gamma = exp(-relu(delta*W + b))
// h_fwd[b,t,j] = h[b, t-(delta-1), j], delta in {1..4} clamped to t+1.
//
// R6: R1's flat shape (one float4 per thread, scattered predicated gathers),
// leaned for occupancy:
//  * coef = (1-m)*gamma with NO delta>1 select: when delta==1 the gather target
//    is ha itself, so hf-ha==0 regardless of coef.
//  * gamma = min(exp(-(d*W+b)), 1) == exp(-relu(d*W+b)): relu folded into one min.
//  * coefs + gather offsets computed and (delta,m,W,b) regs retired BEFORE the
//    ha/gather loads; __launch_bounds__(256,8) pins regs to 32 -> 2048 thr/SM.

#define B_    32
#define T_    2048
#define KD_   256
#define NVCOL 64
#define TPB   256
#define NVEC  (B_ * T_ * NVCOL)   // 4,194,304

__global__ __launch_bounds__(TPB, 8)
void temporal_decay_kernel(const float4* __restrict__ h4,
                           const float4* __restrict__ d4,
                           const float4* __restrict__ m4,
                           const float4* __restrict__ w4,
                           const float4* __restrict__ b4,
                           const float*  __restrict__ hs,
                           float4* __restrict__ out4)
{
    const int i    = blockIdx.x * TPB + threadIdx.x;
    const int row  = i >> 6;            // b*T + t
    const int v    = i & (NVCOL - 1);   // float4 column
    const int base = i << 2;            // scalar index of lane x

    // ---- phase 1: small operands -> coefs + gather predicates/addresses ----
    const float4 dl = d4[(row << 4) + (v & 15)];
    const float4 mm = m4[(row << 4) + (v & 15)];
    const float4 ww = w4[v];
    const float4 bb = b4[v];

    // gamma = min(exp(-(d*W+b)), 1)  (== exp(-relu(.)))
    const float cx = (1.0f - mm.x) * fminf(__expf(-fmaf(dl.x, ww.x, bb.x)), 1.0f);
    const float cy = (1.0f - mm.y) * fminf(__expf(-fmaf(dl.y, ww.y, bb.y)), 1.0f);
    const float cz = (1.0f - mm.z) * fminf(__expf(-fmaf(dl.z, ww.z, bb.z)), 1.0f);
    const float cw = (1.0f - mm.w) * fminf(__expf(-fmaf(dl.w, ww.w, bb.w)), 1.0f);

    // gather scalar addresses: base + c + (1 - delta)*KD_
    const int gax = base     + KD_ - ((int)dl.x << 8);
    const int gay = base + 1 + KD_ - ((int)dl.y << 8);
    const int gaz = base + 2 + KD_ - ((int)dl.z << 8);
    const int gaw = base + 3 + KD_ - ((int)dl.w << 8);

    const bool nx = (cx != 0.0f) && ((int)dl.x > 1);
    const bool ny = (cy != 0.0f) && ((int)dl.y > 1);
    const bool nz = (cz != 0.0f) && ((int)dl.z > 1);
    const bool nw = (cw != 0.0f) && ((int)dl.w > 1);

    // ---- phase 2: bulk data ----
    const float4 ha = h4[i];

    const float hfx = nx ? __ldg(hs + gax) : ha.x;
    const float hfy = ny ? __ldg(hs + gay) : ha.y;
    const float hfz = nz ? __ldg(hs + gaz) : ha.z;
    const float hfw = nw ? __ldg(hs + gaw) : ha.w;

    // ---- phase 3: blend + store ----
    float4 o;
    o.x = fmaf(cx, hfx - ha.x, ha.x);
    o.y = fmaf(cy, hfy - ha.y, ha.y);
    o.z = fmaf(cz, hfz - ha.z, ha.z);
    o.w = fmaf(cw, hfw - ha.w, ha.w);

    out4[i] = o;
}

extern "C" void kernel_launch(void* const* d_in, const int* in_sizes, int n_in,
                              void* d_out, int out_size)
{
    const float* h_a    = (const float*)d_in[0];
    const float* deltas = (const float*)d_in[1];
    const float* M      = (const float*)d_in[2];
    const float* W      = (const float*)d_in[3];
    const float* bvec   = (const float*)d_in[4];
    float* out          = (float*)d_out;

    const int blocks = NVEC / TPB;   // 16384

    temporal_decay_kernel<<<blocks, TPB>>>(
        (const float4*)h_a, (const float4*)deltas, (const float4*)M,
        (const float4*)W, (const float4*)bvec,
        h_a, (float4*)out);
}